// round 10
// baseline (speedup 1.0000x reference)
#include <cuda_runtime.h>
#include <cstdint>
#include <math.h>

#define T_TOK 8192
#define D_DIM 7168
#define E_EXP 256
#define K_TOP 8
#define G_GRP 8
#define LG_GRP 4

// ---- GEMM tiling: CTA 128(M) x 64(N), 256 threads, BK=16, 2 CTAs/SM ----
#define BM 128
#define BN 64
#define BK 16
#define NSTAGE (D_DIM / BK)      // 448

// smem: A duplicated {a,a}: row = 256 floats + 8 pad = 264 floats (1056 B)
//       B: row = 64 floats + 4 pad = 68 floats (272 B)
#define AROWF 264
#define BROWF 68
#define A_BYTES (BK * AROWF * 4)             // 16896
#define B_BYTES (BK * BROWF * 4)             // 4352
#define SMEM_B  (A_BYTES + B_BYTES)          // 21248 -> 2 CTAs/SM

__device__ float g_logits[(size_t)T_TOK * E_EXP];
__device__ int   g_counts[E_EXP];

__device__ __forceinline__ uint32_t smem_to_u32(const void* p) {
    uint32_t a;
    asm("{ .reg .u64 t; cvta.to.shared.u64 t, %1; cvt.u32.u64 %0, t; }" : "=r"(a) : "l"(p));
    return a;
}

// packed f32x2 FMA: d += a * b
#define FFMA2(d, a, b) \
    asm("fma.rn.f32x2 %0, %1, %2, %0;" : "+l"(d) : "l"(a), "l"(b))

// 16B shared load as two packed-f32x2 operands
#define LDS_2U64(r0, r1, addr) \
    asm volatile("ld.shared.v2.u64 {%0, %1}, [%2];" : "=l"(r0), "=l"(r1) : "r"(addr))

// store duplicated float pair {v, v}
#define STS_DUP(addr, v) \
    asm volatile("st.shared.v2.f32 [%0], {%1, %1};" :: "r"(addr), "f"(v) : "memory")

#define STS_F32(addr, v) \
    asm volatile("st.shared.f32 [%0], %1;" :: "r"(addr), "f"(v) : "memory")

// ============ GEMM: C[t][e] = sum_k x[t][k] * W[e][k]  (exact f32) ============
__global__ __launch_bounds__(256, 2)
void gemm_f32x2_kernel(const float* __restrict__ A,   // x [T, D]
                       const float* __restrict__ B,   // W [E, D]
                       float* __restrict__ C)         // logits [T, E]
{
    __shared__ __align__(16) uint8_t smem[SMEM_B];
    const uint32_t sa = smem_to_u32(smem);           // A-dup region
    const uint32_t sbb = sa + A_BYTES;               // B region

    const int tid = threadIdx.x;
    const int tx  = tid & 15;        // n-group: cols tx*4 .. tx*4+3
    const int ty  = tid >> 4;        // m-group: rows ty*8 .. ty*8+7

    const int mb = blockIdx.y * BM;
    const int nb = blockIdx.x * BN;

    // ---- loader mapping ----
    // A: 512 float4 per stage; thread does f4id = tid, tid+256
    const int ar0 = tid >> 2;              // rows for i=0 (0..63), i=1 adds 64
    const int akq = (tid & 3) * 4;         // k-quad base
    const float* Ag = A + (size_t)(mb + ar0) * D_DIM + akq;
    // B: 256 float4 per stage; one per thread
    const int br  = tid >> 2;              // 0..63
    const float* Bg = B + (size_t)(nb + br) * D_DIM + akq;

    // smem store bases
    const uint32_t a_sts = sa + (uint32_t)akq * (AROWF * 4) + (uint32_t)ar0 * 8u;
    const uint32_t b_sts = sbb + (uint32_t)akq * (BROWF * 4) + (uint32_t)br * 4u;

    // compute-side bases
    const uint32_t a_lds = sa + (uint32_t)ty * 64u;          // 8 dup-pairs = 64 B
    const uint32_t b_lds = sbb + (uint32_t)tx * 16u;         // 4 cols = 16 B

    uint64_t acc[8][2];
    #pragma unroll
    for (int i = 0; i < 8; i++) { acc[i][0] = 0ull; acc[i][1] = 0ull; }

    float4 ra0, ra1, rb;

    // prefetch stage 0
    ra0 = *(const float4*)(Ag);
    ra1 = *(const float4*)(Ag + (size_t)64 * D_DIM);
    rb  = *(const float4*)(Bg);

    #pragma unroll 1
    for (int s = 0; s < NSTAGE; s++) {
        __syncthreads();
        // store current stage to smem (A duplicated, B plain)
        {
            const float a0[4] = {ra0.x, ra0.y, ra0.z, ra0.w};
            const float a1[4] = {ra1.x, ra1.y, ra1.z, ra1.w};
            const float bv[4] = {rb.x, rb.y, rb.z, rb.w};
            #pragma unroll
            for (int j = 0; j < 4; j++) {
                STS_DUP(a_sts + (uint32_t)j * (AROWF * 4), a0[j]);
                STS_DUP(a_sts + (uint32_t)j * (AROWF * 4) + 512u, a1[j]);  // rows +64 -> +64*8 B
                STS_F32(b_sts + (uint32_t)j * (BROWF * 4), bv[j]);
            }
        }
        __syncthreads();

        // prefetch next stage into registers (overlaps compute)
        if (s + 1 < NSTAGE) {
            const int k0 = (s + 1) * BK;
            ra0 = *(const float4*)(Ag + k0);
            ra1 = *(const float4*)(Ag + (size_t)64 * D_DIM + k0);
            rb  = *(const float4*)(Bg + k0);
        }

        // compute BK k-steps: per kk, 5 LDS.128 + 16 FFMA2, zero MOVs
        #pragma unroll
        for (int kk = 0; kk < BK; kk++) {
            const uint32_t ka = a_lds + (uint32_t)kk * (AROWF * 4);
            const uint32_t kb = b_lds + (uint32_t)kk * (BROWF * 4);
            uint64_t a64[8], b64[2];
            LDS_2U64(a64[0], a64[1], ka);
            LDS_2U64(a64[2], a64[3], ka + 16u);
            LDS_2U64(a64[4], a64[5], ka + 32u);
            LDS_2U64(a64[6], a64[7], ka + 48u);
            LDS_2U64(b64[0], b64[1], kb);
            #pragma unroll
            for (int i = 0; i < 8; i++) {
                FFMA2(acc[i][0], a64[i], b64[0]);
                FFMA2(acc[i][1], a64[i], b64[1]);
            }
        }
    }

    // ---- epilogue: rows mb+ty*8+i, cols nb+tx*4.. ----
    #pragma unroll
    for (int i = 0; i < 8; i++) {
        float* cp = C + (size_t)(mb + ty * 8 + i) * E_EXP + nb + tx * 4;
        const uint32_t l0 = (uint32_t)acc[i][0], h0 = (uint32_t)(acc[i][0] >> 32);
        const uint32_t l1 = (uint32_t)acc[i][1], h1 = (uint32_t)(acc[i][1] >> 32);
        *(float4*)cp = make_float4(__uint_as_float(l0), __uint_as_float(h0),
                                   __uint_as_float(l1), __uint_as_float(h1));
    }
}

// ================= Routing: one warp per token (proven) =================
__global__ __launch_bounds__(256)
void route_kernel(const float* __restrict__ logits,
                  const float* __restrict__ bias,
                  void* __restrict__ w_out,
                  void* __restrict__ idx_out,
                  int mode)
{
    const float NEG_INF = __int_as_float(0xff800000);
    const int warp = threadIdx.x >> 5;
    const int lane = threadIdx.x & 31;
    const int t = blockIdx.x * 8 + warp;
    if (t >= T_TOK) return;

    const float* lp = logits + (size_t)t * E_EXP;

    float s[8], v[8];
    #pragma unroll
    for (int r = 0; r < 8; r++) {
        float z = __ldg(lp + r * 32 + lane);
        float sig = 1.0f / (1.0f + expf(-z));
        s[r] = sig;
        v[r] = sig + __ldg(bias + r * 32 + lane);
    }

    float gsc[8];
    #pragma unroll
    for (int r = 0; r < 8; r++) {
        float m1 = v[r], m2 = NEG_INF;
        #pragma unroll
        for (int off = 16; off; off >>= 1) {
            float o1 = __shfl_xor_sync(0xffffffffu, m1, off);
            float o2 = __shfl_xor_sync(0xffffffffu, m2, off);
            float hi = fmaxf(m1, o1);
            float lo = fminf(m1, o1);
            m2 = fmaxf(lo, fmaxf(m2, o2));
            m1 = hi;
        }
        gsc[r] = m1 + m2;
    }

    unsigned chosen = 0;
    #pragma unroll
    for (int it = 0; it < LG_GRP; it++) {
        float best = NEG_INF; int bg = 0;
        #pragma unroll
        for (int g = 0; g < G_GRP; g++) {
            bool free_g = ((chosen >> g) & 1u) == 0u;
            if (free_g && gsc[g] > best) { best = gsc[g]; bg = g; }
        }
        chosen |= 1u << bg;
    }
    #pragma unroll
    for (int r = 0; r < 8; r++)
        if (!((chosen >> r) & 1u)) v[r] = NEG_INF;

    float my_w = 0.0f;
    int   my_e = 0;
    #pragma unroll
    for (int k = 0; k < K_TOP; k++) {
        float lb = NEG_INF; int lr = 0;
        #pragma unroll
        for (int r = 0; r < 8; r++)
            if (v[r] > lb) { lb = v[r]; lr = r; }
        float bv = lb;
        int be = lr * 32 + lane;
        #pragma unroll
        for (int off = 16; off; off >>= 1) {
            float ov = __shfl_xor_sync(0xffffffffu, bv, off);
            int   oe = __shfl_xor_sync(0xffffffffu, be, off);
            if (ov > bv || (ov == bv && oe < be)) { bv = ov; be = oe; }
        }
        const int wr = be >> 5, wl = be & 31;
        float sv_sel = 0.0f;
        #pragma unroll
        for (int r = 0; r < 8; r++)
            if (r == wr) sv_sel = s[r];
        float ws = __shfl_sync(0xffffffffu, sv_sel, wl);
        if (lane == k) { my_w = ws; my_e = be; }
        if (lane == wl) {
            #pragma unroll
            for (int r = 0; r < 8; r++)
                if (r == wr) v[r] = NEG_INF;
        }
    }

    float wsum = (lane < K_TOP) ? my_w : 0.0f;
    #pragma unroll
    for (int off = 16; off; off >>= 1)
        wsum += __shfl_xor_sync(0xffffffffu, wsum, off);
    float wfin = my_w * (2.5f / wsum);

    if (lane < K_TOP) {
        const size_t o = (size_t)t * K_TOP + lane;
        if (mode == 2) {   // all-f32 concat (JAX promotion, x64 off)
            ((float*)w_out)[o]   = wfin;
            ((float*)idx_out)[o] = (float)my_e;
        } else {           // byte-concat f32 | i64 | i32
            ((float*)w_out)[o]       = wfin;
            ((long long*)idx_out)[o] = (long long)my_e;
        }
        atomicAdd(&g_counts[my_e], 1);
    }
}

__global__ void zero_counts_kernel() { g_counts[threadIdx.x] = 0; }

__global__ void write_counts_kernel(void* __restrict__ cnt_out, int mode) {
    const int e = threadIdx.x;
    if (mode == 2) ((float*)cnt_out)[e] = (float)g_counts[e];
    else           ((int*)cnt_out)[e]   = g_counts[e];
}

// ================= launch =================
extern "C" void kernel_launch(void* const* d_in, const int* in_sizes, int n_in,
                              void* d_out, int out_size)
{
    const float* x    = (const float*)d_in[0];
    const float* W    = (const float*)d_in[1];
    const float* bias = (const float*)d_in[2];

    char* base = (char*)d_out;
    const size_t TK = (size_t)T_TOK * K_TOP;

    int mode;
    void *w_out, *idx_out, *cnt_out;
    if (out_size == (int)(TK + TK + E_EXP)) {
        mode = 2;
        w_out   = base;
        idx_out = base + TK * 4;
        cnt_out = base + 2 * TK * 4;
    } else {
        mode = 0;
        w_out   = base;
        idx_out = base + TK * 4;
        cnt_out = base + TK * 4 + TK * 8;
    }

    zero_counts_kernel<<<1, E_EXP>>>();

    dim3 grid(E_EXP / BN, T_TOK / BM);   // (4, 64) = 256 CTAs, 2/SM resident
    gemm_f32x2_kernel<<<grid, 256>>>(x, W, g_logits);

    route_kernel<<<T_TOK / 8, 256>>>(g_logits, bias, w_out, idx_out, mode);
    write_counts_kernel<<<1, E_EXP>>>(cnt_out, mode);
}

// round 11
// speedup vs baseline: 1.2649x; 1.2649x over previous
#include <cuda_runtime.h>
#include <cstdint>
#include <math.h>

#define T_TOK 8192
#define D_DIM 7168
#define E_EXP 256
#define K_TOP 8
#define G_GRP 8
#define LG_GRP 4

#define BM 128
#define BN 128
#define BK 16
#define NSTAGE (D_DIM / BK)   // 448
#define PAD 132               // padded smem row (floats)

__device__ float g_logits[(size_t)T_TOK * E_EXP];
__device__ int   g_counts[E_EXP];

// ---------------- packed f32x2 helpers (proven in R2) ----------------
__device__ __forceinline__ uint64_t pack2(float lo, float hi) {
    uint64_t r;
    asm("mov.b64 %0, {%1, %2};" : "=l"(r) : "r"(__float_as_uint(lo)), "r"(__float_as_uint(hi)));
    return r;
}
__device__ __forceinline__ void ffma2(uint64_t& d, uint64_t a, uint64_t b) {
    asm("fma.rn.f32x2 %0, %1, %2, %0;" : "+l"(d) : "l"(a), "l"(b));
}
__device__ __forceinline__ float2 unpack2(uint64_t v) {
    uint32_t lo, hi;
    asm("mov.b64 {%0, %1}, %2;" : "=r"(lo), "=r"(hi) : "l"(v));
    float2 f; f.x = __uint_as_float(lo); f.y = __uint_as_float(hi);
    return f;
}

// ---------------- GEMM: C[t][e] = sum_k x[t][k] * W[e][k] ----------------
// R2's tile/fragment structure; single __syncthreads per stage (double buffer).
__global__ __launch_bounds__(256, 1)
void gemm_kernel(const float* __restrict__ A,   // x [T, D]
                 const float* __restrict__ B,   // W [E, D]
                 float* __restrict__ C)         // logits [T, E]
{
    __shared__ float As[2][BK][PAD];
    __shared__ float Bs[2][BK][PAD];

    const int tid = threadIdx.x;
    const int tx = tid & 15;        // col group (8 cols each)
    const int ty = tid >> 4;        // row group (8 rows each)
    const int tile_n = blockIdx.x;  // 0..1
    const int tile_m = blockIdx.y;  // 0..63

    const float* Ab = A + (size_t)tile_m * BM * D_DIM;
    const float* Bb = B + (size_t)tile_n * BN * D_DIM;

    const int lr = tid >> 2;          // 0..63
    const int lc = (tid & 3) * 4;     // 0,4,8,12

    uint64_t acc[8][4];
    #pragma unroll
    for (int i = 0; i < 8; i++)
        #pragma unroll
        for (int j = 0; j < 4; j++) acc[i][j] = 0ull;

    float4 a0, a1, b0, b1;

    // ---- prologue: stage 0 -> buf 0 ----
    a0 = *(const float4*)(Ab + (size_t)lr * D_DIM + lc);
    a1 = *(const float4*)(Ab + (size_t)(lr + 64) * D_DIM + lc);
    b0 = *(const float4*)(Bb + (size_t)lr * D_DIM + lc);
    b1 = *(const float4*)(Bb + (size_t)(lr + 64) * D_DIM + lc);
    As[0][lc + 0][lr] = a0.x; As[0][lc + 1][lr] = a0.y; As[0][lc + 2][lr] = a0.z; As[0][lc + 3][lr] = a0.w;
    As[0][lc + 0][lr + 64] = a1.x; As[0][lc + 1][lr + 64] = a1.y; As[0][lc + 2][lr + 64] = a1.z; As[0][lc + 3][lr + 64] = a1.w;
    Bs[0][lc + 0][lr] = b0.x; Bs[0][lc + 1][lr] = b0.y; Bs[0][lc + 2][lr] = b0.z; Bs[0][lc + 3][lr] = b0.w;
    Bs[0][lc + 0][lr + 64] = b1.x; Bs[0][lc + 1][lr + 64] = b1.y; Bs[0][lc + 2][lr + 64] = b1.z; Bs[0][lc + 3][lr + 64] = b1.w;
    __syncthreads();

    // prefetch stage 1 into registers
    a0 = *(const float4*)(Ab + (size_t)lr * D_DIM + BK + lc);
    a1 = *(const float4*)(Ab + (size_t)(lr + 64) * D_DIM + BK + lc);
    b0 = *(const float4*)(Bb + (size_t)lr * D_DIM + BK + lc);
    b1 = *(const float4*)(Bb + (size_t)(lr + 64) * D_DIM + BK + lc);

    #pragma unroll 1
    for (int s = 0; s < NSTAGE; s++) {
        const int cb = s & 1;
        const int nb = (s + 1) & 1;

        // store stage s+1 into the other buffer (consumed through iteration
        // s-1, protected by the trailing barrier)
        if (s + 1 < NSTAGE) {
            As[nb][lc + 0][lr] = a0.x; As[nb][lc + 1][lr] = a0.y; As[nb][lc + 2][lr] = a0.z; As[nb][lc + 3][lr] = a0.w;
            As[nb][lc + 0][lr + 64] = a1.x; As[nb][lc + 1][lr + 64] = a1.y; As[nb][lc + 2][lr + 64] = a1.z; As[nb][lc + 3][lr + 64] = a1.w;
            Bs[nb][lc + 0][lr] = b0.x; Bs[nb][lc + 1][lr] = b0.y; Bs[nb][lc + 2][lr] = b0.z; Bs[nb][lc + 3][lr] = b0.w;
            Bs[nb][lc + 0][lr + 64] = b1.x; Bs[nb][lc + 1][lr + 64] = b1.y; Bs[nb][lc + 2][lr + 64] = b1.z; Bs[nb][lc + 3][lr + 64] = b1.w;
        }
        // prefetch stage s+2 into registers (overlaps compute)
        if (s + 2 < NSTAGE) {
            const int k0 = (s + 2) * BK;
            a0 = *(const float4*)(Ab + (size_t)lr * D_DIM + k0 + lc);
            a1 = *(const float4*)(Ab + (size_t)(lr + 64) * D_DIM + k0 + lc);
            b0 = *(const float4*)(Bb + (size_t)lr * D_DIM + k0 + lc);
            b1 = *(const float4*)(Bb + (size_t)(lr + 64) * D_DIM + k0 + lc);
        }

        // compute stage s (R2's proven inner loop)
        #pragma unroll
        for (int kk = 0; kk < BK; kk++) {
            float4 av0 = *(const float4*)&As[cb][kk][ty * 8];
            float4 av1 = *(const float4*)&As[cb][kk][ty * 8 + 4];
            float4 bv0 = *(const float4*)&Bs[cb][kk][tx * 8];
            float4 bv1 = *(const float4*)&Bs[cb][kk][tx * 8 + 4];
            uint64_t bp[4];
            bp[0] = pack2(bv0.x, bv0.y);
            bp[1] = pack2(bv0.z, bv0.w);
            bp[2] = pack2(bv1.x, bv1.y);
            bp[3] = pack2(bv1.z, bv1.w);
            float av[8] = {av0.x, av0.y, av0.z, av0.w, av1.x, av1.y, av1.z, av1.w};
            #pragma unroll
            for (int i = 0; i < 8; i++) {
                uint64_t ap = pack2(av[i], av[i]);
                #pragma unroll
                for (int j = 0; j < 4; j++) ffma2(acc[i][j], ap, bp[j]);
            }
        }
        __syncthreads();
    }

    // ---- epilogue: write 8x8 tile ----
    const int row0 = tile_m * BM + ty * 8;
    const int col0 = tile_n * BN + tx * 8;
    #pragma unroll
    for (int i = 0; i < 8; i++) {
        float2 c0 = unpack2(acc[i][0]);
        float2 c1 = unpack2(acc[i][1]);
        float2 c2 = unpack2(acc[i][2]);
        float2 c3 = unpack2(acc[i][3]);
        float* cp = C + (size_t)(row0 + i) * E_EXP + col0;
        *(float4*)(cp)     = make_float4(c0.x, c0.y, c1.x, c1.y);
        *(float4*)(cp + 4) = make_float4(c2.x, c2.y, c3.x, c3.y);
    }
}

// ================= Routing: one warp per token (proven) =================
__global__ __launch_bounds__(256)
void route_kernel(const float* __restrict__ logits,
                  const float* __restrict__ bias,
                  void* __restrict__ w_out,
                  void* __restrict__ idx_out,
                  int mode)
{
    const float NEG_INF = __int_as_float(0xff800000);
    const int warp = threadIdx.x >> 5;
    const int lane = threadIdx.x & 31;
    const int t = blockIdx.x * 8 + warp;
    if (t >= T_TOK) return;

    const float* lp = logits + (size_t)t * E_EXP;

    float s[8], v[8];
    #pragma unroll
    for (int r = 0; r < 8; r++) {
        float z = __ldg(lp + r * 32 + lane);
        float sig = 1.0f / (1.0f + expf(-z));
        s[r] = sig;
        v[r] = sig + __ldg(bias + r * 32 + lane);
    }

    float gsc[8];
    #pragma unroll
    for (int r = 0; r < 8; r++) {
        float m1 = v[r], m2 = NEG_INF;
        #pragma unroll
        for (int off = 16; off; off >>= 1) {
            float o1 = __shfl_xor_sync(0xffffffffu, m1, off);
            float o2 = __shfl_xor_sync(0xffffffffu, m2, off);
            float hi = fmaxf(m1, o1);
            float lo = fminf(m1, o1);
            m2 = fmaxf(lo, fmaxf(m2, o2));
            m1 = hi;
        }
        gsc[r] = m1 + m2;
    }

    unsigned chosen = 0;
    #pragma unroll
    for (int it = 0; it < LG_GRP; it++) {
        float best = NEG_INF; int bg = 0;
        #pragma unroll
        for (int g = 0; g < G_GRP; g++) {
            bool free_g = ((chosen >> g) & 1u) == 0u;
            if (free_g && gsc[g] > best) { best = gsc[g]; bg = g; }
        }
        chosen |= 1u << bg;
    }
    #pragma unroll
    for (int r = 0; r < 8; r++)
        if (!((chosen >> r) & 1u)) v[r] = NEG_INF;

    float my_w = 0.0f;
    int   my_e = 0;
    #pragma unroll
    for (int k = 0; k < K_TOP; k++) {
        float lb = NEG_INF; int lr = 0;
        #pragma unroll
        for (int r = 0; r < 8; r++)
            if (v[r] > lb) { lb = v[r]; lr = r; }
        float bv = lb;
        int be = lr * 32 + lane;
        #pragma unroll
        for (int off = 16; off; off >>= 1) {
            float ov = __shfl_xor_sync(0xffffffffu, bv, off);
            int   oe = __shfl_xor_sync(0xffffffffu, be, off);
            if (ov > bv || (ov == bv && oe < be)) { bv = ov; be = oe; }
        }
        const int wr = be >> 5, wl = be & 31;
        float sv_sel = 0.0f;
        #pragma unroll
        for (int r = 0; r < 8; r++)
            if (r == wr) sv_sel = s[r];
        float ws = __shfl_sync(0xffffffffu, sv_sel, wl);
        if (lane == k) { my_w = ws; my_e = be; }
        if (lane == wl) {
            #pragma unroll
            for (int r = 0; r < 8; r++)
                if (r == wr) v[r] = NEG_INF;
        }
    }

    float wsum = (lane < K_TOP) ? my_w : 0.0f;
    #pragma unroll
    for (int off = 16; off; off >>= 1)
        wsum += __shfl_xor_sync(0xffffffffu, wsum, off);
    float wfin = my_w * (2.5f / wsum);

    if (lane < K_TOP) {
        const size_t o = (size_t)t * K_TOP + lane;
        if (mode == 2) {   // all-f32 concat (JAX promotion, x64 off)
            ((float*)w_out)[o]   = wfin;
            ((float*)idx_out)[o] = (float)my_e;
        } else {           // byte-concat f32 | i64 | i32
            ((float*)w_out)[o]       = wfin;
            ((long long*)idx_out)[o] = (long long)my_e;
        }
        atomicAdd(&g_counts[my_e], 1);
    }
}

__global__ void zero_counts_kernel() { g_counts[threadIdx.x] = 0; }

__global__ void write_counts_kernel(void* __restrict__ cnt_out, int mode) {
    const int e = threadIdx.x;
    if (mode == 2) ((float*)cnt_out)[e] = (float)g_counts[e];
    else           ((int*)cnt_out)[e]   = g_counts[e];
}

// ================= launch =================
extern "C" void kernel_launch(void* const* d_in, const int* in_sizes, int n_in,
                              void* d_out, int out_size)
{
    const float* x    = (const float*)d_in[0];
    const float* W    = (const float*)d_in[1];
    const float* bias = (const float*)d_in[2];

    char* base = (char*)d_out;
    const size_t TK = (size_t)T_TOK * K_TOP;

    int mode;
    void *w_out, *idx_out, *cnt_out;
    if (out_size == (int)(TK + TK + E_EXP)) {
        mode = 2;
        w_out   = base;
        idx_out = base + TK * 4;
        cnt_out = base + 2 * TK * 4;
    } else {
        mode = 0;
        w_out   = base;
        idx_out = base + TK * 4;
        cnt_out = base + TK * 4 + TK * 8;
    }

    zero_counts_kernel<<<1, E_EXP>>>();

    dim3 grid(E_EXP / BN, T_TOK / BM);   // (2, 64) = 128 CTAs
    gemm_kernel<<<grid, 256>>>(x, W, g_logits);

    route_kernel<<<T_TOK / 8, 256>>>(g_logits, bias, w_out, idx_out, mode);
    write_counts_kernel<<<1, E_EXP>>>(cnt_out, mode);
}